// round 13
// baseline (speedup 1.0000x reference)
#include <cuda_runtime.h>

// Fused FFT-butterfly MLP. 2 rows per CTA, register-resident butterflies,
// SIMD-across-rows f32x2 arithmetic, and a PRE-BROADCAST packed twiddle
// table in smem: each entry is ulonglong2 {(c,c),(s,s)} so a twiddle load
// is one LDS.128 with zero broadcast MOVs.
// Stages 1-3: register bits. Stages 4-8: lane<->reg bit swaps + local
// butterflies. Stage 9 via broadcast-twiddle shuffle; 10-12 register bits.
// Layer 2 stages 11/12 compute only surviving (i < 1024) outputs.

#define N_FFT    4096
#define HALF_N   2048
#define BATCH    4096
#define OUT_C    1024
#define NT       512

#define DATA_F4  4608              // ulonglong2 units: 4096 + 512 pad (i + (i>>3))
#define TW_U2    2176              // ulonglong2 units: 2048 + 128 pad (k + (k>>4))
#define SMEM_BYTES ((DATA_F4 + TW_U2) * (int)sizeof(ulonglong2))   // 108544

typedef unsigned long long ull;

__device__ __align__(16) float2 g_tw1[HALF_N];
__device__ __align__(16) float2 g_tw2[HALF_N];

__global__ void twiddle_kernel(const float* __restrict__ w1,
                               const float* __restrict__ w2) {
    int k = blockIdx.x * blockDim.x + threadIdx.x;
    if (k < HALF_N) {
        const float c = -6.283185307179586f / (float)N_FFT;
        float kk = (float)k;
        float s, co;
        sincosf(c * kk * w1[k], &s, &co);
        g_tw1[k] = make_float2(co, s);
        sincosf(c * kk * w2[k], &s, &co);
        g_tw2[k] = make_float2(co, s);
    }
}

__device__ __forceinline__ int padD(int i) { return i + (i >> 3); }
__device__ __forceinline__ int padT(int k) { return k + (k >> 4); }

// ---- packed f32x2 primitives ----
#define F2MUL(d, a, b)    asm("mul.rn.f32x2 %0, %1, %2;"     : "=l"(d) : "l"(a), "l"(b))
#define F2ADD(d, a, b)    asm("add.rn.f32x2 %0, %1, %2;"     : "=l"(d) : "l"(a), "l"(b))
#define F2FMA(d, a, b, c) asm("fma.rn.f32x2 %0, %1, %2, %3;" : "=l"(d) : "l"(a), "l"(b), "l"(c))

__device__ __forceinline__ ull pack2(float lo, float hi) {
    ull r; asm("mov.b64 %0, {%1, %2};" : "=l"(r) : "f"(lo), "f"(hi)); return r;
}
__device__ __forceinline__ float lo32(ull u) { return __uint_as_float((unsigned)u); }
__device__ __forceinline__ float hi32(ull u) { return __uint_as_float((unsigned)(u >> 32)); }

struct PC { ull cc, ss; };   // twiddle broadcast: (c,c), (s,s)
// Pre-broadcast table: one LDS.128, no MOVs.
__device__ __forceinline__ PC ldtw(const ulonglong2* __restrict__ TWP, int kpad) {
    ulonglong2 e = TWP[kpad];
    PC p; p.cc = e.x; p.ss = e.y; return p;
}

// packed butterfly on both rows: a' = a + w*b ; b' = a - w*b   (9 packed ops)
__device__ __forceinline__ void bfp(ull& aX, ull& aY, ull& bX, ull& bY,
                                    const PC w, const ull N1) {
    ull q, p, tX, r2, tY, nbX, nbY;
    F2MUL(q, w.cc, bX); F2MUL(p, w.ss, bY); F2FMA(tX, N1, p, q);   // t.x = c*bx - s*by
    F2MUL(r2, w.cc, bY); F2FMA(tY, w.ss, bX, r2);                  // t.y = c*by + s*bx
    F2FMA(nbX, N1, tX, aX); F2FMA(nbY, N1, tY, aY);                // b' = a - t
    F2ADD(aX, aX, tX); F2ADD(aY, aY, tY);                          // a' = a + t
    bX = nbX; bY = nbY;
}
// tw = 1 butterfly (4 packed ops)
__device__ __forceinline__ void bf1p(ull& aX, ull& aY, ull& bX, ull& bY,
                                     const ull N1) {
    ull nbX, nbY;
    F2FMA(nbX, N1, bX, aX); F2FMA(nbY, N1, bY, aY);
    F2ADD(aX, aX, bX); F2ADD(aY, aY, bY);
    bX = nbX; bY = nbY;
}
// half-butterfly: a' = a + w*b only (5 packed ops)
__device__ __forceinline__ void hbfp(ull& aX, ull& aY, const ull bX, const ull bY,
                                     const PC w, const ull N1) {
    ull t1, p, t2;
    F2FMA(t1, w.cc, bX, aX); F2MUL(p, w.ss, bY); F2FMA(aX, N1, p, t1);
    F2FMA(t2, w.cc, bY, aY); F2FMA(aY, w.ss, bX, t2);
}

// Swap lane bit m with register bit rho (both packed arrays; 8 b64 SHFL).
__device__ __forceinline__ void swap_lrp(ull* XP, ull* YP, int lane, int m, int rho) {
    bool hi = (lane & m) != 0;
    #pragma unroll
    for (int n = 0; n < 8; n++) {
        if (n & rho) continue;
        int nh = n | rho;
        ull sx = hi ? XP[n] : XP[nh];
        sx = __shfl_xor_sync(0xffffffffu, sx, m);
        if (hi) XP[n] = sx; else XP[nh] = sx;
        ull sy = hi ? YP[n] : YP[nh];
        sy = __shfl_xor_sync(0xffffffffu, sy, m);
        if (hi) YP[n] = sy; else YP[nh] = sy;
    }
}

// Stages 1-8. Input: A layout (i = 8t + r). Output layout (folded into the
// exchange store): lanes l0..l4 = i0..i4, regs r0,r1,r2 = i6,i7,i5.
__device__ __forceinline__ void stages_1_8(ull* XP, ull* YP, int lane,
                                           const ulonglong2* __restrict__ TWP,
                                           const ull N1) {
    // S1: bit 0, tw = 1
    bf1p(XP[0],YP[0],XP[1],YP[1],N1); bf1p(XP[2],YP[2],XP[3],YP[3],N1);
    bf1p(XP[4],YP[4],XP[5],YP[5],N1); bf1p(XP[6],YP[6],XP[7],YP[7],N1);
    // S2: bit 1, k = (r&1)<<10 ; tw(0) = 1
    {
        PC tB = ldtw(TWP, padT(1 << 10));
        bf1p(XP[0],YP[0],XP[2],YP[2],N1); bfp(XP[1],YP[1],XP[3],YP[3],tB,N1);
        bf1p(XP[4],YP[4],XP[6],YP[6],N1); bfp(XP[5],YP[5],XP[7],YP[7],tB,N1);
    }
    // S3: bit 2, k = (r&3)<<9 ; tw(0) = 1
    {
        PC t1 = ldtw(TWP, padT(1 << 9));
        PC t2 = ldtw(TWP, padT(2 << 9));
        PC t3 = ldtw(TWP, padT(3 << 9));
        bf1p(XP[0],YP[0],XP[4],YP[4],N1);
        bfp(XP[1],YP[1],XP[5],YP[5],t1,N1);
        bfp(XP[2],YP[2],XP[6],YP[6],t2,N1);
        bfp(XP[3],YP[3],XP[7],YP[7],t3,N1);
    }
    // S4: swap(l0, rb0); j = l0 + 2*i1 + 4*i2
    {
        swap_lrp(XP, YP, lane, 1, 1);
        int l0 = lane & 1;
        PC t0 = ldtw(TWP, padT((l0 + 0) << 8));
        PC t1 = ldtw(TWP, padT((l0 + 2) << 8));
        PC t2 = ldtw(TWP, padT((l0 + 4) << 8));
        PC t3 = ldtw(TWP, padT((l0 + 6) << 8));
        bfp(XP[0],YP[0],XP[1],YP[1],t0,N1);
        bfp(XP[2],YP[2],XP[3],YP[3],t1,N1);
        bfp(XP[4],YP[4],XP[5],YP[5],t2,N1);
        bfp(XP[6],YP[6],XP[7],YP[7],t3,N1);
    }
    // S5: swap(l1, rb1); j = (lane&3) + 4*i2(rb2) + 8*i3(rb0)
    {
        swap_lrp(XP, YP, lane, 2, 2);
        int l01 = lane & 3;
        PC t0 = ldtw(TWP, padT((l01 + 0)  << 7));
        PC t1 = ldtw(TWP, padT((l01 + 8)  << 7));
        PC t2 = ldtw(TWP, padT((l01 + 4)  << 7));
        PC t3 = ldtw(TWP, padT((l01 + 12) << 7));
        bfp(XP[0],YP[0],XP[2],YP[2],t0,N1);
        bfp(XP[1],YP[1],XP[3],YP[3],t1,N1);
        bfp(XP[4],YP[4],XP[6],YP[6],t2,N1);
        bfp(XP[5],YP[5],XP[7],YP[7],t3,N1);
    }
    // S6: swap(l2, rb2); j = (lane&7) + 8*i3(rb0) + 16*i4(rb1)
    {
        swap_lrp(XP, YP, lane, 4, 4);
        int l02 = lane & 7;
        PC t0 = ldtw(TWP, padT((l02 + 0)  << 6));
        PC t1 = ldtw(TWP, padT((l02 + 8)  << 6));
        PC t2 = ldtw(TWP, padT((l02 + 16) << 6));
        PC t3 = ldtw(TWP, padT((l02 + 24) << 6));
        bfp(XP[0],YP[0],XP[4],YP[4],t0,N1);
        bfp(XP[1],YP[1],XP[5],YP[5],t1,N1);
        bfp(XP[2],YP[2],XP[6],YP[6],t2,N1);
        bfp(XP[3],YP[3],XP[7],YP[7],t3,N1);
    }
    // S7: swap(l3, rb0); j = (lane&15) + 16*i4(rb1) + 32*i5(rb2)
    {
        swap_lrp(XP, YP, lane, 8, 1);
        int l03 = lane & 15;
        PC t0 = ldtw(TWP, padT((l03 + 0)  << 5));
        PC t1 = ldtw(TWP, padT((l03 + 16) << 5));
        PC t2 = ldtw(TWP, padT((l03 + 32) << 5));
        PC t3 = ldtw(TWP, padT((l03 + 48) << 5));
        bfp(XP[0],YP[0],XP[1],YP[1],t0,N1);
        bfp(XP[2],YP[2],XP[3],YP[3],t1,N1);
        bfp(XP[4],YP[4],XP[5],YP[5],t2,N1);
        bfp(XP[6],YP[6],XP[7],YP[7],t3,N1);
    }
    // S8: swap(l4, rb1); j = lane + 32*i5(rb2) + 64*i6(rb0)
    {
        swap_lrp(XP, YP, lane, 16, 2);
        PC t0 = ldtw(TWP, padT((lane + 0)  << 4));
        PC t1 = ldtw(TWP, padT((lane + 64) << 4));
        PC t2 = ldtw(TWP, padT((lane + 32) << 4));
        PC t3 = ldtw(TWP, padT((lane + 96) << 4));
        bfp(XP[0],YP[0],XP[2],YP[2],t0,N1);
        bfp(XP[1],YP[1],XP[3],YP[3],t1,N1);
        bfp(XP[4],YP[4],XP[6],YP[6],t2,N1);
        bfp(XP[5],YP[5],XP[7],YP[7],t3,N1);
    }
}

// True element index of register n after stages_1_8:
// i = lane + 32*c(n) + 256*w, with c(n) = i5 + 2*i6 + 4*i7
__device__ __forceinline__ int cmap(int n) {
    return ((n >> 2) & 1) + 2 * (n & 1) + 4 * ((n >> 1) & 1);
}

// Stages 9-10 on D-layout registers (i = tid9 | (r<<9)).
__device__ __forceinline__ void stages_9_10(ull* XP, ull* YP, int lane, int tid9,
                                            const ulonglong2* __restrict__ TWP,
                                            const ull N1) {
    // S9: bit 8 = lane bit 0 ; k = (i & 255) << 3, uniform over r
    {
        bool up = (lane & 1) != 0;
        PC w = ldtw(TWP, padT((tid9 & 255) << 3));
        #pragma unroll
        for (int r = 0; r < 8; r++) {
            ull vX = XP[r], vY = YP[r];
            ull pX = __shfl_xor_sync(0xffffffffu, vX, 1);
            ull pY = __shfl_xor_sync(0xffffffffu, vY, 1);
            ull q, p2, tX, r2, tY;
            if (up) {   // own = b, partner = a : result = a - w*b
                F2MUL(q, w.cc, vX); F2MUL(p2, w.ss, vY); F2FMA(tX, N1, p2, q);
                F2MUL(r2, w.cc, vY); F2FMA(tY, w.ss, vX, r2);
                F2FMA(XP[r], N1, tX, pX); F2FMA(YP[r], N1, tY, pY);
            } else {    // own = a, partner = b : result = a + w*b
                F2MUL(q, w.cc, pX); F2MUL(p2, w.ss, pY); F2FMA(tX, N1, p2, q);
                F2MUL(r2, w.cc, pY); F2FMA(tY, w.ss, pX, r2);
                F2ADD(XP[r], vX, tX); F2ADD(YP[r], vY, tY);
            }
        }
    }
    // S10: bit 9 = r bit 0 ; k = tid9<<2
    {
        PC w = ldtw(TWP, padT(tid9 << 2));
        bfp(XP[0],YP[0],XP[1],YP[1],w,N1);
        bfp(XP[2],YP[2],XP[3],YP[3],w,N1);
        bfp(XP[4],YP[4],XP[5],YP[5],w,N1);
        bfp(XP[6],YP[6],XP[7],YP[7],w,N1);
    }
}

// Full stages 11-12 (layer 1).
__device__ __forceinline__ void stages_11_12_full(ull* XP, ull* YP, int tid9,
                                                  const ulonglong2* __restrict__ TWP,
                                                  const ull N1) {
    {
        PC tA = ldtw(TWP, padT(tid9 << 1));
        PC tB = ldtw(TWP, padT((tid9 | 512) << 1));
        bfp(XP[0],YP[0],XP[2],YP[2],tA,N1);
        bfp(XP[1],YP[1],XP[3],YP[3],tB,N1);
        bfp(XP[4],YP[4],XP[6],YP[6],tA,N1);
        bfp(XP[5],YP[5],XP[7],YP[7],tB,N1);
    }
    {
        PC t0 = ldtw(TWP, padT(tid9));
        PC t1 = ldtw(TWP, padT(tid9 | (1 << 9)));
        PC t2 = ldtw(TWP, padT(tid9 | (2 << 9)));
        PC t3 = ldtw(TWP, padT(tid9 | (3 << 9)));
        bfp(XP[0],YP[0],XP[4],YP[4],t0,N1);
        bfp(XP[1],YP[1],XP[5],YP[5],t1,N1);
        bfp(XP[2],YP[2],XP[6],YP[6],t2,N1);
        bfp(XP[3],YP[3],XP[7],YP[7],t3,N1);
    }
}

// Truncated stages 11-12 (layer 2): only i < 1024 outputs (r in {0,1}).
__device__ __forceinline__ void stages_11_12_trunc(ull* XP, ull* YP, int tid9,
                                                   const ulonglong2* __restrict__ TWP,
                                                   const ull N1) {
    {
        PC tA = ldtw(TWP, padT(tid9 << 1));
        PC tB = ldtw(TWP, padT((tid9 | 512) << 1));
        hbfp(XP[0],YP[0],XP[2],YP[2],tA,N1);
        hbfp(XP[1],YP[1],XP[3],YP[3],tB,N1);
        hbfp(XP[4],YP[4],XP[6],YP[6],tA,N1);
        hbfp(XP[5],YP[5],XP[7],YP[7],tB,N1);
    }
    {
        PC t0 = ldtw(TWP, padT(tid9));
        PC t1 = ldtw(TWP, padT(tid9 | (1 << 9)));
        hbfp(XP[0],YP[0],XP[4],YP[4],t0,N1);
        hbfp(XP[1],YP[1],XP[5],YP[5],t1,N1);
    }
}

__device__ __forceinline__ ull relup(ull u) {
    return pack2(fmaxf(lo32(u), 0.f), fmaxf(hi32(u), 0.f));
}

__global__ __launch_bounds__(NT, 2)
void mlp_fft_kernel(const float2* __restrict__ xin, float2* __restrict__ out) {
    extern __shared__ ulonglong2 smU[];
    ulonglong2* SD  = smU;                 // DATA_F4 entries (XP, YP packed)
    ulonglong2* TWP = smU + DATA_F4;       // TW_U2 pre-broadcast twiddles

    const int t    = threadIdx.x;
    const int lane = t & 31;
    const int w    = t >> 5;
    const int tid9 = (w << 4) | (lane >> 1) | ((lane & 1) << 8);
    const int rowA = 2 * blockIdx.x;
    const ull N1   = pack2(-1.0f, -1.0f);

    ull XP[8], YP[8];

    // --- Stage twiddles 1 pre-broadcast; load inputs packed (perm ^2048) ---
    #pragma unroll
    for (int u = 0; u < 2; u++) {
        int k = 2 * (t + u * NT);              // 2 twiddles per float4
        float4 v = ((const float4*)g_tw1)[t + u * NT];
        TWP[padT(k)]     = make_ulonglong2(pack2(v.x, v.x), pack2(v.y, v.y));
        TWP[padT(k) + 1] = make_ulonglong2(pack2(v.z, v.z), pack2(v.w, v.w));
    }
    {
        const float4* xa4 = (const float4*)(xin + (size_t)rowA * N_FFT);
        const float4* xb4 = xa4 + N_FFT / 2;
        #pragma unroll
        for (int c = 0; c < 4; c++) {
            float4 v  = __ldg(&xa4[(4 * t + c) ^ 1024]);
            float4 vb = __ldg(&xb4[(4 * t + c) ^ 1024]);
            XP[2 * c]     = pack2(v.x, vb.x);
            YP[2 * c]     = pack2(v.y, vb.y);
            XP[2 * c + 1] = pack2(v.z, vb.z);
            YP[2 * c + 1] = pack2(v.w, vb.w);
        }
    }
    __syncthreads();   // TW1 ready

    // ================= Layer 1 =================
    stages_1_8(XP, YP, lane, TWP, N1);

    // Exchange (permuted A) -> D
    #pragma unroll
    for (int n = 0; n < 8; n++)
        SD[padD(lane + 32 * cmap(n) + 256 * w)] = make_ulonglong2(XP[n], YP[n]);
    __syncthreads();
    #pragma unroll
    for (int r = 0; r < 8; r++) {
        ulonglong2 e = SD[padD(tid9 | (r << 9))];
        XP[r] = e.x; YP[r] = e.y;
    }

    stages_9_10(XP, YP, lane, tid9, TWP, N1);
    stages_11_12_full(XP, YP, tid9, TWP, N1);

    // ReLU (elementwise, commutes with the perm) + perm ^2048 (r ^= 4)
    #pragma unroll
    for (int r = 0; r < 8; r++) { XP[r] = relup(XP[r]); YP[r] = relup(YP[r]); }
    #pragma unroll
    for (int r = 0; r < 4; r++) {
        ull tx = XP[r]; XP[r] = XP[r + 4]; XP[r + 4] = tx;
        ull ty = YP[r]; YP[r] = YP[r + 4]; YP[r + 4] = ty;
    }

    // Exchange D -> A, swap twiddle table to layer 2
    __syncthreads();   // prior readers done
    #pragma unroll
    for (int r = 0; r < 8; r++)
        SD[padD(tid9 | (r << 9))] = make_ulonglong2(XP[r], YP[r]);
    #pragma unroll
    for (int u = 0; u < 2; u++) {
        int k = 2 * (t + u * NT);
        float4 v = ((const float4*)g_tw2)[t + u * NT];
        TWP[padT(k)]     = make_ulonglong2(pack2(v.x, v.x), pack2(v.y, v.y));
        TWP[padT(k) + 1] = make_ulonglong2(pack2(v.z, v.z), pack2(v.w, v.w));
    }
    __syncthreads();
    #pragma unroll
    for (int r = 0; r < 8; r++) {
        ulonglong2 e = SD[padD(8 * t + r)];
        XP[r] = e.x; YP[r] = e.y;
    }

    // ================= Layer 2 =================
    stages_1_8(XP, YP, lane, TWP, N1);

    __syncthreads();   // prior A-layout readers done
    #pragma unroll
    for (int n = 0; n < 8; n++)
        SD[padD(lane + 32 * cmap(n) + 256 * w)] = make_ulonglong2(XP[n], YP[n]);
    __syncthreads();
    #pragma unroll
    for (int r = 0; r < 8; r++) {
        ulonglong2 e = SD[padD(tid9 | (r << 9))];
        XP[r] = e.x; YP[r] = e.y;
    }

    stages_9_10(XP, YP, lane, tid9, TWP, N1);
    stages_11_12_trunc(XP, YP, tid9, TWP, N1);

    // Output: regs r in {0,1}; row A = lo halves, row B = hi halves
    {
        float2* oa = out + (size_t)rowA * OUT_C;
        oa[tid9]               = make_float2(lo32(XP[0]), lo32(YP[0]));
        oa[tid9 + 512]         = make_float2(lo32(XP[1]), lo32(YP[1]));
        oa[OUT_C + tid9]       = make_float2(hi32(XP[0]), hi32(YP[0]));
        oa[OUT_C + tid9 + 512] = make_float2(hi32(XP[1]), hi32(YP[1]));
    }
}

extern "C" void kernel_launch(void* const* d_in, const int* in_sizes, int n_in,
                              void* d_out, int out_size) {
    const float* x  = (const float*)d_in[0];   // (4096, 8192) f32
    const float* w1 = (const float*)d_in[1];   // (2048,) f32
    const float* w2 = (const float*)d_in[2];   // (2048,) f32
    float* out = (float*)d_out;                // (4096, 2048) f32

    cudaFuncSetAttribute(mlp_fft_kernel,
                         cudaFuncAttributeMaxDynamicSharedMemorySize, SMEM_BYTES);

    twiddle_kernel<<<2, 1024>>>(w1, w2);
    mlp_fft_kernel<<<BATCH / 2, NT, SMEM_BYTES>>>((const float2*)x, (float2*)out);
}

// round 16
// speedup vs baseline: 1.3035x; 1.3035x over previous
#include <cuda_runtime.h>

// Fused FFT-butterfly MLP. 2 rows per CTA, register-resident butterflies,
// SIMD-across-rows f32x2 arithmetic. Twiddle table stored as float2 (8B) --
// pre-broadcast 16B entries were tried and REGRESSED 30% (doubled LDS
// wavefronts on lane-divergent loads); the 4 broadcast MOVs per twiddle on
// the underutilized ALU pipe are cheaper. (R13 post-mortem.)
// Stages 1-3: register bits. Stages 4-8: lane<->reg bit swaps + local
// butterflies. Stage 9 via broadcast-twiddle shuffle; 10-12 register bits.
// Layer 2 stages 11/12 compute only surviving (i < 1024) outputs.
// Verified config: 143.4 us (R12).

#define N_FFT    4096
#define HALF_N   2048
#define BATCH    4096
#define OUT_C    1024
#define NT       512

#define DATA_F4  4608              // ulonglong2 units: 4096 + 512 pad (i + (i>>3))
#define TW_F2    2176              // float2 units: 2048 + 128 pad (k + (k>>4))
#define SMEM_BYTES (DATA_F4 * (int)sizeof(ulonglong2) + TW_F2 * (int)sizeof(float2))

typedef unsigned long long ull;

__device__ __align__(16) float2 g_tw1[HALF_N];
__device__ __align__(16) float2 g_tw2[HALF_N];

__global__ void twiddle_kernel(const float* __restrict__ w1,
                               const float* __restrict__ w2) {
    int k = blockIdx.x * blockDim.x + threadIdx.x;
    if (k < HALF_N) {
        const float c = -6.283185307179586f / (float)N_FFT;
        float kk = (float)k;
        float s, co;
        sincosf(c * kk * w1[k], &s, &co);
        g_tw1[k] = make_float2(co, s);
        sincosf(c * kk * w2[k], &s, &co);
        g_tw2[k] = make_float2(co, s);
    }
}

__device__ __forceinline__ int padD(int i) { return i + (i >> 3); }
__device__ __forceinline__ int padT(int k) { return k + (k >> 4); }

// ---- packed f32x2 primitives ----
#define F2MUL(d, a, b)    asm("mul.rn.f32x2 %0, %1, %2;"     : "=l"(d) : "l"(a), "l"(b))
#define F2ADD(d, a, b)    asm("add.rn.f32x2 %0, %1, %2;"     : "=l"(d) : "l"(a), "l"(b))
#define F2FMA(d, a, b, c) asm("fma.rn.f32x2 %0, %1, %2, %3;" : "=l"(d) : "l"(a), "l"(b), "l"(c))

__device__ __forceinline__ ull pack2(float lo, float hi) {
    ull r; asm("mov.b64 %0, {%1, %2};" : "=l"(r) : "f"(lo), "f"(hi)); return r;
}
__device__ __forceinline__ float lo32(ull u) { return __uint_as_float((unsigned)u); }
__device__ __forceinline__ float hi32(ull u) { return __uint_as_float((unsigned)(u >> 32)); }

struct PC { ull cc, ss; };   // twiddle broadcast: (c,c), (s,s)
__device__ __forceinline__ PC ldtw(const float2* __restrict__ TW, int kpad) {
    float2 t = TW[kpad];
    PC p; p.cc = pack2(t.x, t.x); p.ss = pack2(t.y, t.y); return p;
}

// packed butterfly on both rows: a' = a + w*b ; b' = a - w*b   (9 packed ops)
__device__ __forceinline__ void bfp(ull& aX, ull& aY, ull& bX, ull& bY,
                                    const PC w, const ull N1) {
    ull q, p, tX, r2, tY, nbX, nbY;
    F2MUL(q, w.cc, bX); F2MUL(p, w.ss, bY); F2FMA(tX, N1, p, q);   // t.x = c*bx - s*by
    F2MUL(r2, w.cc, bY); F2FMA(tY, w.ss, bX, r2);                  // t.y = c*by + s*bx
    F2FMA(nbX, N1, tX, aX); F2FMA(nbY, N1, tY, aY);                // b' = a - t
    F2ADD(aX, aX, tX); F2ADD(aY, aY, tY);                          // a' = a + t
    bX = nbX; bY = nbY;
}
// tw = 1 butterfly (4 packed ops)
__device__ __forceinline__ void bf1p(ull& aX, ull& aY, ull& bX, ull& bY,
                                     const ull N1) {
    ull nbX, nbY;
    F2FMA(nbX, N1, bX, aX); F2FMA(nbY, N1, bY, aY);
    F2ADD(aX, aX, bX); F2ADD(aY, aY, bY);
    bX = nbX; bY = nbY;
}
// half-butterfly: a' = a + w*b only (5 packed ops)
__device__ __forceinline__ void hbfp(ull& aX, ull& aY, const ull bX, const ull bY,
                                     const PC w, const ull N1) {
    ull t1, p, t2;
    F2FMA(t1, w.cc, bX, aX); F2MUL(p, w.ss, bY); F2FMA(aX, N1, p, t1);
    F2FMA(t2, w.cc, bY, aY); F2FMA(aY, w.ss, bX, t2);
}

// Swap lane bit m with register bit rho (both packed arrays; 8 b64 SHFL).
__device__ __forceinline__ void swap_lrp(ull* XP, ull* YP, int lane, int m, int rho) {
    bool hi = (lane & m) != 0;
    #pragma unroll
    for (int n = 0; n < 8; n++) {
        if (n & rho) continue;
        int nh = n | rho;
        ull sx = hi ? XP[n] : XP[nh];
        sx = __shfl_xor_sync(0xffffffffu, sx, m);
        if (hi) XP[n] = sx; else XP[nh] = sx;
        ull sy = hi ? YP[n] : YP[nh];
        sy = __shfl_xor_sync(0xffffffffu, sy, m);
        if (hi) YP[n] = sy; else YP[nh] = sy;
    }
}

// Stages 1-8. Input: A layout (i = 8t + r). Output layout (folded into the
// exchange store): lanes l0..l4 = i0..i4, regs r0,r1,r2 = i6,i7,i5.
__device__ __forceinline__ void stages_1_8(ull* XP, ull* YP, int lane,
                                           const float2* __restrict__ TW,
                                           const ull N1) {
    // S1: bit 0, tw = 1
    bf1p(XP[0],YP[0],XP[1],YP[1],N1); bf1p(XP[2],YP[2],XP[3],YP[3],N1);
    bf1p(XP[4],YP[4],XP[5],YP[5],N1); bf1p(XP[6],YP[6],XP[7],YP[7],N1);
    // S2: bit 1, k = (r&1)<<10 ; tw(0) = 1
    {
        PC tB = ldtw(TW, padT(1 << 10));
        bf1p(XP[0],YP[0],XP[2],YP[2],N1); bfp(XP[1],YP[1],XP[3],YP[3],tB,N1);
        bf1p(XP[4],YP[4],XP[6],YP[6],N1); bfp(XP[5],YP[5],XP[7],YP[7],tB,N1);
    }
    // S3: bit 2, k = (r&3)<<9 ; tw(0) = 1
    {
        PC t1 = ldtw(TW, padT(1 << 9));
        PC t2 = ldtw(TW, padT(2 << 9));
        PC t3 = ldtw(TW, padT(3 << 9));
        bf1p(XP[0],YP[0],XP[4],YP[4],N1);
        bfp(XP[1],YP[1],XP[5],YP[5],t1,N1);
        bfp(XP[2],YP[2],XP[6],YP[6],t2,N1);
        bfp(XP[3],YP[3],XP[7],YP[7],t3,N1);
    }
    // S4: swap(l0, rb0); j = l0 + 2*i1 + 4*i2
    {
        swap_lrp(XP, YP, lane, 1, 1);
        int l0 = lane & 1;
        PC t0 = ldtw(TW, padT((l0 + 0) << 8));
        PC t1 = ldtw(TW, padT((l0 + 2) << 8));
        PC t2 = ldtw(TW, padT((l0 + 4) << 8));
        PC t3 = ldtw(TW, padT((l0 + 6) << 8));
        bfp(XP[0],YP[0],XP[1],YP[1],t0,N1);
        bfp(XP[2],YP[2],XP[3],YP[3],t1,N1);
        bfp(XP[4],YP[4],XP[5],YP[5],t2,N1);
        bfp(XP[6],YP[6],XP[7],YP[7],t3,N1);
    }
    // S5: swap(l1, rb1); j = (lane&3) + 4*i2(rb2) + 8*i3(rb0)
    {
        swap_lrp(XP, YP, lane, 2, 2);
        int l01 = lane & 3;
        PC t0 = ldtw(TW, padT((l01 + 0)  << 7));
        PC t1 = ldtw(TW, padT((l01 + 8)  << 7));
        PC t2 = ldtw(TW, padT((l01 + 4)  << 7));
        PC t3 = ldtw(TW, padT((l01 + 12) << 7));
        bfp(XP[0],YP[0],XP[2],YP[2],t0,N1);
        bfp(XP[1],YP[1],XP[3],YP[3],t1,N1);
        bfp(XP[4],YP[4],XP[6],YP[6],t2,N1);
        bfp(XP[5],YP[5],XP[7],YP[7],t3,N1);
    }
    // S6: swap(l2, rb2); j = (lane&7) + 8*i3(rb0) + 16*i4(rb1)
    {
        swap_lrp(XP, YP, lane, 4, 4);
        int l02 = lane & 7;
        PC t0 = ldtw(TW, padT((l02 + 0)  << 6));
        PC t1 = ldtw(TW, padT((l02 + 8)  << 6));
        PC t2 = ldtw(TW, padT((l02 + 16) << 6));
        PC t3 = ldtw(TW, padT((l02 + 24) << 6));
        bfp(XP[0],YP[0],XP[4],YP[4],t0,N1);
        bfp(XP[1],YP[1],XP[5],YP[5],t1,N1);
        bfp(XP[2],YP[2],XP[6],YP[6],t2,N1);
        bfp(XP[3],YP[3],XP[7],YP[7],t3,N1);
    }
    // S7: swap(l3, rb0); j = (lane&15) + 16*i4(rb1) + 32*i5(rb2)
    {
        swap_lrp(XP, YP, lane, 8, 1);
        int l03 = lane & 15;
        PC t0 = ldtw(TW, padT((l03 + 0)  << 5));
        PC t1 = ldtw(TW, padT((l03 + 16) << 5));
        PC t2 = ldtw(TW, padT((l03 + 32) << 5));
        PC t3 = ldtw(TW, padT((l03 + 48) << 5));
        bfp(XP[0],YP[0],XP[1],YP[1],t0,N1);
        bfp(XP[2],YP[2],XP[3],YP[3],t1,N1);
        bfp(XP[4],YP[4],XP[5],YP[5],t2,N1);
        bfp(XP[6],YP[6],XP[7],YP[7],t3,N1);
    }
    // S8: swap(l4, rb1); j = lane + 32*i5(rb2) + 64*i6(rb0)
    {
        swap_lrp(XP, YP, lane, 16, 2);
        PC t0 = ldtw(TW, padT((lane + 0)  << 4));
        PC t1 = ldtw(TW, padT((lane + 64) << 4));
        PC t2 = ldtw(TW, padT((lane + 32) << 4));
        PC t3 = ldtw(TW, padT((lane + 96) << 4));
        bfp(XP[0],YP[0],XP[2],YP[2],t0,N1);
        bfp(XP[1],YP[1],XP[3],YP[3],t1,N1);
        bfp(XP[4],YP[4],XP[6],YP[6],t2,N1);
        bfp(XP[5],YP[5],XP[7],YP[7],t3,N1);
    }
}

// True element index of register n after stages_1_8:
// i = lane + 32*c(n) + 256*w, with c(n) = i5 + 2*i6 + 4*i7
__device__ __forceinline__ int cmap(int n) {
    return ((n >> 2) & 1) + 2 * (n & 1) + 4 * ((n >> 1) & 1);
}

// Stages 9-10 on D-layout registers (i = tid9 | (r<<9)).
__device__ __forceinline__ void stages_9_10(ull* XP, ull* YP, int lane, int tid9,
                                            const float2* __restrict__ TW,
                                            const ull N1) {
    // S9: bit 8 = lane bit 0 ; k = (i & 255) << 3, uniform over r
    {
        bool up = (lane & 1) != 0;
        PC w = ldtw(TW, padT((tid9 & 255) << 3));
        #pragma unroll
        for (int r = 0; r < 8; r++) {
            ull vX = XP[r], vY = YP[r];
            ull pX = __shfl_xor_sync(0xffffffffu, vX, 1);
            ull pY = __shfl_xor_sync(0xffffffffu, vY, 1);
            ull q, p2, tX, r2, tY;
            if (up) {   // own = b, partner = a : result = a - w*b
                F2MUL(q, w.cc, vX); F2MUL(p2, w.ss, vY); F2FMA(tX, N1, p2, q);
                F2MUL(r2, w.cc, vY); F2FMA(tY, w.ss, vX, r2);
                F2FMA(XP[r], N1, tX, pX); F2FMA(YP[r], N1, tY, pY);
            } else {    // own = a, partner = b : result = a + w*b
                F2MUL(q, w.cc, pX); F2MUL(p2, w.ss, pY); F2FMA(tX, N1, p2, q);
                F2MUL(r2, w.cc, pY); F2FMA(tY, w.ss, pX, r2);
                F2ADD(XP[r], vX, tX); F2ADD(YP[r], vY, tY);
            }
        }
    }
    // S10: bit 9 = r bit 0 ; k = tid9<<2
    {
        PC w = ldtw(TW, padT(tid9 << 2));
        bfp(XP[0],YP[0],XP[1],YP[1],w,N1);
        bfp(XP[2],YP[2],XP[3],YP[3],w,N1);
        bfp(XP[4],YP[4],XP[5],YP[5],w,N1);
        bfp(XP[6],YP[6],XP[7],YP[7],w,N1);
    }
}

// Full stages 11-12 (layer 1).
__device__ __forceinline__ void stages_11_12_full(ull* XP, ull* YP, int tid9,
                                                  const float2* __restrict__ TW,
                                                  const ull N1) {
    {
        PC tA = ldtw(TW, padT(tid9 << 1));
        PC tB = ldtw(TW, padT((tid9 | 512) << 1));
        bfp(XP[0],YP[0],XP[2],YP[2],tA,N1);
        bfp(XP[1],YP[1],XP[3],YP[3],tB,N1);
        bfp(XP[4],YP[4],XP[6],YP[6],tA,N1);
        bfp(XP[5],YP[5],XP[7],YP[7],tB,N1);
    }
    {
        PC t0 = ldtw(TW, padT(tid9));
        PC t1 = ldtw(TW, padT(tid9 | (1 << 9)));
        PC t2 = ldtw(TW, padT(tid9 | (2 << 9)));
        PC t3 = ldtw(TW, padT(tid9 | (3 << 9)));
        bfp(XP[0],YP[0],XP[4],YP[4],t0,N1);
        bfp(XP[1],YP[1],XP[5],YP[5],t1,N1);
        bfp(XP[2],YP[2],XP[6],YP[6],t2,N1);
        bfp(XP[3],YP[3],XP[7],YP[7],t3,N1);
    }
}

// Truncated stages 11-12 (layer 2): only i < 1024 outputs (r in {0,1}).
__device__ __forceinline__ void stages_11_12_trunc(ull* XP, ull* YP, int tid9,
                                                   const float2* __restrict__ TW,
                                                   const ull N1) {
    {
        PC tA = ldtw(TW, padT(tid9 << 1));
        PC tB = ldtw(TW, padT((tid9 | 512) << 1));
        hbfp(XP[0],YP[0],XP[2],YP[2],tA,N1);
        hbfp(XP[1],YP[1],XP[3],YP[3],tB,N1);
        hbfp(XP[4],YP[4],XP[6],YP[6],tA,N1);
        hbfp(XP[5],YP[5],XP[7],YP[7],tB,N1);
    }
    {
        PC t0 = ldtw(TW, padT(tid9));
        PC t1 = ldtw(TW, padT(tid9 | (1 << 9)));
        hbfp(XP[0],YP[0],XP[4],YP[4],t0,N1);
        hbfp(XP[1],YP[1],XP[5],YP[5],t1,N1);
    }
}

__device__ __forceinline__ ull relup(ull u) {
    return pack2(fmaxf(lo32(u), 0.f), fmaxf(hi32(u), 0.f));
}

__global__ __launch_bounds__(NT, 2)
void mlp_fft_kernel(const float2* __restrict__ xin, float2* __restrict__ out) {
    extern __shared__ ulonglong2 smU[];
    ulonglong2* SD = smU;                      // DATA_F4 entries (XP, YP packed)
    float2* TW = (float2*)(smU + DATA_F4);     // TW_F2 float2

    const int t    = threadIdx.x;
    const int lane = t & 31;
    const int w    = t >> 5;
    const int tid9 = (w << 4) | (lane >> 1) | ((lane & 1) << 8);
    const int rowA = 2 * blockIdx.x;
    const ull N1   = pack2(-1.0f, -1.0f);

    ull XP[8], YP[8];

    // --- Stage twiddles 1; load inputs packed across rows (perm ^2048) ---
    #pragma unroll
    for (int u = 0; u < 2; u++) {
        int k = 2 * (t + u * NT);              // even k: padT(k+1) == padT(k)+1
        float4 v = ((const float4*)g_tw1)[t + u * NT];
        TW[padT(k)]     = make_float2(v.x, v.y);
        TW[padT(k) + 1] = make_float2(v.z, v.w);
    }
    {
        const float4* xa4 = (const float4*)(xin + (size_t)rowA * N_FFT);
        const float4* xb4 = xa4 + N_FFT / 2;
        #pragma unroll
        for (int c = 0; c < 4; c++) {
            float4 v  = __ldg(&xa4[(4 * t + c) ^ 1024]);
            float4 vb = __ldg(&xb4[(4 * t + c) ^ 1024]);
            XP[2 * c]     = pack2(v.x, vb.x);
            YP[2 * c]     = pack2(v.y, vb.y);
            XP[2 * c + 1] = pack2(v.z, vb.z);
            YP[2 * c + 1] = pack2(v.w, vb.w);
        }
    }
    __syncthreads();   // TW1 ready

    // ================= Layer 1 =================
    stages_1_8(XP, YP, lane, TW, N1);

    // Exchange (permuted A) -> D
    #pragma unroll
    for (int n = 0; n < 8; n++)
        SD[padD(lane + 32 * cmap(n) + 256 * w)] = make_ulonglong2(XP[n], YP[n]);
    __syncthreads();
    #pragma unroll
    for (int r = 0; r < 8; r++) {
        ulonglong2 e = SD[padD(tid9 | (r << 9))];
        XP[r] = e.x; YP[r] = e.y;
    }

    stages_9_10(XP, YP, lane, tid9, TW, N1);
    stages_11_12_full(XP, YP, tid9, TW, N1);

    // ReLU (elementwise, commutes with the perm) + perm ^2048 (r ^= 4)
    #pragma unroll
    for (int r = 0; r < 8; r++) { XP[r] = relup(XP[r]); YP[r] = relup(YP[r]); }
    #pragma unroll
    for (int r = 0; r < 4; r++) {
        ull tx = XP[r]; XP[r] = XP[r + 4]; XP[r + 4] = tx;
        ull ty = YP[r]; YP[r] = YP[r + 4]; YP[r + 4] = ty;
    }

    // Exchange D -> A, swap twiddle table to layer 2
    __syncthreads();   // prior readers done
    #pragma unroll
    for (int r = 0; r < 8; r++)
        SD[padD(tid9 | (r << 9))] = make_ulonglong2(XP[r], YP[r]);
    #pragma unroll
    for (int u = 0; u < 2; u++) {
        int k = 2 * (t + u * NT);
        float4 v = ((const float4*)g_tw2)[t + u * NT];
        TW[padT(k)]     = make_float2(v.x, v.y);
        TW[padT(k) + 1] = make_float2(v.z, v.w);
    }
    __syncthreads();
    #pragma unroll
    for (int r = 0; r < 8; r++) {
        ulonglong2 e = SD[padD(8 * t + r)];
        XP[r] = e.x; YP[r] = e.y;
    }

    // ================= Layer 2 =================
    stages_1_8(XP, YP, lane, TW, N1);

    __syncthreads();   // prior A-layout readers done
    #pragma unroll
    for (int n = 0; n < 8; n++)
        SD[padD(lane + 32 * cmap(n) + 256 * w)] = make_ulonglong2(XP[n], YP[n]);
    __syncthreads();
    #pragma unroll
    for (int r = 0; r < 8; r++) {
        ulonglong2 e = SD[padD(tid9 | (r << 9))];
        XP[r] = e.x; YP[r] = e.y;
    }

    stages_9_10(XP, YP, lane, tid9, TW, N1);
    stages_11_12_trunc(XP, YP, tid9, TW, N1);

    // Output: regs r in {0,1}; row A = lo halves, row B = hi halves
    {
        float2* oa = out + (size_t)rowA * OUT_C;
        oa[tid9]               = make_float2(lo32(XP[0]), lo32(YP[0]));
        oa[tid9 + 512]         = make_float2(lo32(XP[1]), lo32(YP[1]));
        oa[OUT_C + tid9]       = make_float2(hi32(XP[0]), hi32(YP[0]));
        oa[OUT_C + tid9 + 512] = make_float2(hi32(XP[1]), hi32(YP[1]));
    }
}

extern "C" void kernel_launch(void* const* d_in, const int* in_sizes, int n_in,
                              void* d_out, int out_size) {
    const float* x  = (const float*)d_in[0];   // (4096, 8192) f32
    const float* w1 = (const float*)d_in[1];   // (2048,) f32
    const float* w2 = (const float*)d_in[2];   // (2048,) f32
    float* out = (float*)d_out;                // (4096, 2048) f32

    cudaFuncSetAttribute(mlp_fft_kernel,
                         cudaFuncAttributeMaxDynamicSharedMemorySize, SMEM_BYTES);

    twiddle_kernel<<<2, 1024>>>(w1, w2);
    mlp_fft_kernel<<<BATCH / 2, NT, SMEM_BYTES>>>((const float2*)x, (float2*)out);
}